// round 12
// baseline (speedup 1.0000x reference)
#include <cuda_runtime.h>
#include <cuda_fp16.h>
#include <cstdint>
#include <cstddef>

// ---------------- problem constants ----------------
#define N_ENT      100000
#define N_RELS     401
#define N_BASES    50
#define D          128
#define N_EDGES_C  800000
#define N_TRIPLES_C 4096
#define BN_EPS     1e-5f
#define SCAN_BLKS  98             // 98 * 1024 >= 100000

// ---------------- scratch ----------------
__device__ float g_r0[N_RELS * D];
__device__ float g_r1[N_RELS * D];
__device__ __half g_rh[N_RELS * D];                    // fp16 gather copy of current r
__device__ __half g_xh[(size_t)N_ENT * D];             // fp16 gather table (25.6 MB)
__device__ __half g_agg3h[(size_t)3 * N_ENT * D];      // per-class aggregates, fp16 (76.8 MB)
__device__ __half g_X1h[(size_t)N_ENT * D];            // layer-1 pre-BN output (fp16)
__device__ __half g_X2h[(size_t)N_ENT * D];            // layer-2 pre-BN output (fp16)
__device__ float g_sums[2 * D];
__device__ float g_sumsq[2 * D];
__device__ __half g_Wh[6 * D * D];                     // fp16 W1[0..2], W2[0..2]
// CSR
__device__ int g_deg[N_ENT];
__device__ int g_rs[N_ENT];            // after k_perm: END offset per dst
__device__ int g_bsum[SCAN_BLKS];
__device__ int2 g_edge[N_EDGES_C];     // (src, et | y<<16)

// ---------------- helpers ----------------
__device__ __forceinline__ uint32_t smem_u32(const void* p) {
    uint32_t a;
    asm("{ .reg .u64 t; cvta.to.shared.u64 t, %1; cvt.u32.u64 %0, t; }" : "=r"(a) : "l"(p));
    return a;
}
__device__ __forceinline__ uint32_t pkh(float a, float b) {
    __half2 t = __floats2half2_rn(a, b);
    return *reinterpret_cast<uint32_t*>(&t);
}
__device__ __forceinline__ void ldsm_x4(uint32_t* r, uint32_t addr) {
    asm volatile("ldmatrix.sync.aligned.m8n8.x4.shared.b16 {%0,%1,%2,%3}, [%4];"
                 : "=r"(r[0]), "=r"(r[1]), "=r"(r[2]), "=r"(r[3]) : "r"(addr));
}
__device__ __forceinline__ void ldsm_x4_t(uint32_t* r, uint32_t addr) {
    asm volatile("ldmatrix.sync.aligned.m8n8.x4.trans.shared.b16 {%0,%1,%2,%3}, [%4];"
                 : "=r"(r[0]), "=r"(r[1]), "=r"(r[2]), "=r"(r[3]) : "r"(addr));
}
__device__ __forceinline__ void mma16816(float* c, const uint32_t* a, const uint32_t* b) {
    asm volatile(
        "mma.sync.aligned.m16n8k16.row.col.f32.f16.f16.f32 "
        "{%0,%1,%2,%3}, {%4,%5,%6,%7}, {%8,%9}, {%0,%1,%2,%3};"
        : "+f"(c[0]), "+f"(c[1]), "+f"(c[2]), "+f"(c[3])
        : "r"(a[0]), "r"(a[1]), "r"(a[2]), "r"(a[3]), "r"(b[0]), "r"(b[1]));
}
__device__ __forceinline__ void acc4(float4& a, const uint2& xv, const uint2& rv) {
    float2 x01 = __half22float2(*reinterpret_cast<const __half2*>(&xv.x));
    float2 x23 = __half22float2(*reinterpret_cast<const __half2*>(&xv.y));
    float2 r01 = __half22float2(*reinterpret_cast<const __half2*>(&rv.x));
    float2 r23 = __half22float2(*reinterpret_cast<const __half2*>(&rv.y));
    a.x += x01.x - r01.x; a.y += x01.y - r01.y;
    a.z += x23.x - r23.x; a.w += x23.y - r23.y;
}

// ============ prep0: W fp16 x6 + stats zero + r0/rh + deg zero + entity fp16 ==
// grid: [0,6) W | [6,207) r0 | [207,598) deg zero | [598,13098) entity conv
__global__ void k_prep0(const float* __restrict__ W1,
                        const float* __restrict__ W2,
                        const float* __restrict__ coeff,
                        const float* __restrict__ bases,
                        const float* __restrict__ selfr,
                        const float* __restrict__ entity) {
    int b = blockIdx.x;
    int tid = threadIdx.x;
    if (b < 6) {
        if (b == 0 && tid < 256) { g_sums[tid] = 0.f; g_sumsq[tid] = 0.f; }
        const float* W = (b < 3) ? (W1 + b * D * D) : (W2 + (b - 3) * D * D);
#pragma unroll
        for (int i = 0; i < 64; ++i)
            g_Wh[b * D * D + tid + i * 256] = __float2half(W[tid + i * 256]);
        return;
    }
    if (b < 207) {
        int rb = b - 6;
        int c = tid;
        if (rb == 200) {
            if (c < 128) {
                float v = selfr[c];
                g_r0[400 * D + c] = v;
                g_rh[400 * D + c] = __float2half(v);
            }
            return;
        }
        __shared__ float co[N_BASES];
        if (c < N_BASES) co[c] = coeff[rb * N_BASES + c];
        __syncthreads();
        if (c >= 128) return;
        float acc = 0.f;
#pragma unroll
        for (int i = 0; i < N_BASES; ++i) acc += co[i] * bases[i * D + c];
        g_r0[rb * D + c] = acc;
        g_r0[(200 + rb) * D + c] = -acc;
        g_rh[rb * D + c] = __float2half(acc);
        g_rh[(200 + rb) * D + c] = __float2half(-acc);
        return;
    }
    if (b < 598) {
        int i = (b - 207) * 256 + tid;
        if (i < N_ENT) g_deg[i] = 0;
        return;
    }
    int i = (b - 598) * 256 + tid;
    if (i < N_ENT * D / 4) {
        float4 v = reinterpret_cast<const float4*>(entity)[i];
        reinterpret_cast<uint2*>(g_xh)[i] = make_uint2(pkh(v.x, v.y), pkh(v.z, v.w));
    }
}

// ================= CSR build =================
__global__ void k_hist(const int* __restrict__ ei) {
    int e = blockIdx.x * blockDim.x + threadIdx.x;
    if (e < N_EDGES_C) atomicAdd(&g_deg[ei[N_EDGES_C + e]], 1);
}
__global__ void k_scan1() {
    __shared__ int ts[256];
    int b = blockIdx.x, t = threadIdx.x;
    int base = b * 1024 + t * 4;
    int v[4];
#pragma unroll
    for (int j = 0; j < 4; ++j)
        v[j] = (base + j < N_ENT) ? g_deg[base + j] : 0;
    int s = v[0] + v[1] + v[2] + v[3];
    ts[t] = s;
    __syncthreads();
    for (int off = 1; off < 256; off <<= 1) {
        int x = (t >= off) ? ts[t - off] : 0;
        __syncthreads();
        ts[t] += x;
        __syncthreads();
    }
    int excl = ts[t] - s;
    if (t == 255) g_bsum[b] = ts[255];
#pragma unroll
    for (int j = 0; j < 4; ++j) {
        if (base + j < N_ENT) g_rs[base + j] = excl;
        excl += v[j];
    }
}
__global__ void k_scan3() {
    __shared__ int ts[128];
    __shared__ int s_pref[128];
    int t = threadIdx.x;
    int v0 = 0;
    if (t < 128) {
        v0 = (t < SCAN_BLKS) ? g_bsum[t] : 0;
        ts[t] = v0;
    }
    __syncthreads();
    for (int off = 1; off < 128; off <<= 1) {
        int x = (t >= off && t < 128) ? ts[t - off] : 0;
        __syncthreads();
        if (t < 128) ts[t] += x;
        __syncthreads();
    }
    if (t < 128) s_pref[t] = ts[t] - v0;
    __syncthreads();
    int i = blockIdx.x * 256 + t;
    if (i < N_ENT) g_rs[i] += s_pref[i >> 10];
}
__global__ void k_perm(const int* __restrict__ ei,
                       const int* __restrict__ et,
                       const int* __restrict__ yv) {
    int e = blockIdx.x * blockDim.x + threadIdx.x;
    if (e >= N_EDGES_C) return;
    int dst = ei[N_EDGES_C + e];
    int pos = atomicAdd(&g_rs[dst], 1);          // g_rs ends as END offset
    g_edge[pos] = make_int2(ei[e], et[e] | (yv[e] << 16));
}

// ================= per-dst aggregation (fp16 gather -> fp16 agg3) ===========
__global__ __launch_bounds__(256) void k_aggr() {
    int d = blockIdx.x * 8 + (threadIdx.x >> 5);
    if (d >= N_ENT) return;
    int lane = threadIdx.x & 31;
    int end = g_rs[d];
    int i = end - g_deg[d];
    float4 a0 = make_float4(0.f, 0.f, 0.f, 0.f), a1 = a0, a2 = a0;
    for (; i + 1 < end; i += 2) {
        int2 e0 = __ldg(&g_edge[i]);
        int2 e1 = __ldg(&g_edge[i + 1]);
        uint2 x0 = __ldg(reinterpret_cast<const uint2*>(g_xh + (size_t)e0.x * D) + lane);
        uint2 x1 = __ldg(reinterpret_cast<const uint2*>(g_xh + (size_t)e1.x * D) + lane);
        uint2 r0v = __ldg(reinterpret_cast<const uint2*>(g_rh + (size_t)(e0.y & 0xFFFF) * D) + lane);
        uint2 r1v = __ldg(reinterpret_cast<const uint2*>(g_rh + (size_t)(e1.y & 0xFFFF) * D) + lane);
        int y0 = e0.y >> 16, y1 = e1.y >> 16;
        if (y0 == 0) acc4(a0, x0, r0v); else if (y0 == 1) acc4(a1, x0, r0v); else acc4(a2, x0, r0v);
        if (y1 == 0) acc4(a0, x1, r1v); else if (y1 == 1) acc4(a1, x1, r1v); else acc4(a2, x1, r1v);
    }
    if (i < end) {
        int2 e0 = __ldg(&g_edge[i]);
        uint2 x0 = __ldg(reinterpret_cast<const uint2*>(g_xh + (size_t)e0.x * D) + lane);
        uint2 r0v = __ldg(reinterpret_cast<const uint2*>(g_rh + (size_t)(e0.y & 0xFFFF) * D) + lane);
        int y0 = e0.y >> 16;
        if (y0 == 0) acc4(a0, x0, r0v); else if (y0 == 1) acc4(a1, x0, r0v); else acc4(a2, x0, r0v);
    }
    uint2* o0 = reinterpret_cast<uint2*>(g_agg3h + (size_t)d * D) + lane;
    uint2* o1 = reinterpret_cast<uint2*>(g_agg3h + ((size_t)N_ENT + d) * D) + lane;
    uint2* o2 = reinterpret_cast<uint2*>(g_agg3h + ((size_t)2 * N_ENT + d) * D) + lane;
    *o0 = make_uint2(pkh(a0.x, a0.y), pkh(a0.z, a0.w));
    *o1 = make_uint2(pkh(a1.x, a1.y), pkh(a1.z, a1.w));
    *o2 = make_uint2(pkh(a2.x, a2.y), pkh(a2.z, a2.w));
}

// ============ GEMM: out = sum_k agg3h[k] @ W[k], fused BN stats, fp16 out ====
#define AP 136
#define A_TILE_B (64 * AP * 2)          // 17408
#define W_TILE_B (128 * AP * 2)         // 34816
#define SMEM_DYN (A_TILE_B + W_TILE_B)  // 52224
#define GEMM_BLKS 1563                  // ceil(100000/64)
__global__ __launch_bounds__(256, 4) void k_gemm(__half* __restrict__ outp,
                                                 const __half* __restrict__ Wset,
                                                 float* __restrict__ sums,
                                                 float* __restrict__ sumsq) {
    extern __shared__ unsigned char sm[];
    __half* sA = reinterpret_cast<__half*>(sm);
    __half* sW = reinterpret_cast<__half*>(sm + A_TILE_B);
    __shared__ float s_sum[D], s_sq[D];

    const int tid = threadIdx.x, wid = tid >> 5, lane = tid & 31;
    const int row0 = blockIdx.x * 64;
    const int wm = wid >> 1, wn = wid & 1;
    const int mbase = wm * 16, nbase = wn * 64;

    if (tid < D) { s_sum[tid] = 0.f; s_sq[tid] = 0.f; }

    const uint32_t uA = smem_u32(sA), uW = smem_u32(sW);

    float acc[8][4];
#pragma unroll
    for (int i = 0; i < 8; ++i)
#pragma unroll
        for (int j = 0; j < 4; ++j) acc[i][j] = 0.f;

    for (int k = 0; k < 3; ++k) {
        __syncthreads();
        const uint4* gw = reinterpret_cast<const uint4*>(Wset + k * D * D);
#pragma unroll
        for (int i = 0; i < 8; ++i) {
            int idx = tid + i * 256;
            int r = idx >> 4, c8 = (idx & 15) * 8;
            *reinterpret_cast<uint4*>(sW + r * AP + c8) = gw[idx];
        }
        const __half* ga = g_agg3h + (size_t)k * N_ENT * D;
#pragma unroll
        for (int i = 0; i < 4; ++i) {
            int idx = tid + i * 256;
            int r = idx >> 4, c8 = (idx & 15) * 8;
            int grow = row0 + r;
            uint4 v = make_uint4(0u, 0u, 0u, 0u);
            if (grow < N_ENT)
                v = *reinterpret_cast<const uint4*>(ga + (size_t)grow * D + c8);
            *reinterpret_cast<uint4*>(sA + r * AP + c8) = v;
        }
        __syncthreads();

#pragma unroll
        for (int ks = 0; ks < 8; ++ks) {
            const int k0 = ks * 16;
            uint32_t ah[4];
            {
                int row = mbase + (lane & 15);
                int col = k0 + (lane >> 4) * 8;
                ldsm_x4(ah, uA + (uint32_t)(row * AP + col) * 2);
            }
            uint32_t bh[8][2];
#pragma unroll
            for (int p = 0; p < 4; ++p) {
                int row = k0 + ((lane >> 3) & 1) * 8 + (lane & 7);
                int col = nbase + p * 16 + (lane >> 4) * 8;
                uint32_t t4[4];
                ldsm_x4_t(t4, uW + (uint32_t)(row * AP + col) * 2);
                bh[2 * p][0] = t4[0]; bh[2 * p][1] = t4[1];
                bh[2 * p + 1][0] = t4[2]; bh[2 * p + 1][1] = t4[3];
            }
#pragma unroll
            for (int nt = 0; nt < 8; ++nt)
                mma16816(acc[nt], ah, bh[nt]);
        }
    }

    const int g = lane >> 2, t2 = (lane & 3) * 2;
    int r0 = row0 + mbase + g;
    int r1 = r0 + 8;
    bool ok0 = r0 < N_ENT, ok1 = r1 < N_ENT;
#pragma unroll
    for (int nt = 0; nt < 8; ++nt) {
        int col = nbase + nt * 8 + t2;
        if (ok0)
            *reinterpret_cast<uint32_t*>(outp + (size_t)r0 * D + col) =
                pkh(acc[nt][0], acc[nt][1]);
        if (ok1)
            *reinterpret_cast<uint32_t*>(outp + (size_t)r1 * D + col) =
                pkh(acc[nt][2], acc[nt][3]);
        float a0 = ok0 ? acc[nt][0] : 0.f, a1 = ok0 ? acc[nt][1] : 0.f;
        float a2 = ok1 ? acc[nt][2] : 0.f, a3 = ok1 ? acc[nt][3] : 0.f;
        float se = a0 + a2, so = a1 + a3;
        float qe = a0 * a0 + a2 * a2, qo = a1 * a1 + a3 * a3;
#pragma unroll
        for (int off = 16; off >= 4; off >>= 1) {
            se += __shfl_down_sync(0xffffffffu, se, off);
            so += __shfl_down_sync(0xffffffffu, so, off);
            qe += __shfl_down_sync(0xffffffffu, qe, off);
            qo += __shfl_down_sync(0xffffffffu, qo, off);
        }
        if (lane < 4) {
            atomicAdd(&s_sum[col], se);
            atomicAdd(&s_sum[col + 1], so);
            atomicAdd(&s_sq[col], qe);
            atomicAdd(&s_sq[col + 1], qo);
        }
    }
    __syncthreads();
    if (tid < D) {
        atomicAdd(&sums[tid], s_sum[tid]);
        atomicAdd(&sumsq[tid], s_sq[tid]);
    }
}

// ======== post1: rel1 (r1 fp32 + rh fp16) blocks + bn-tanh blocks ===========
// grid: [0,401) rel | [401,1183) bntanh (each covers 4096 uint2 elems)
__global__ void k_post1(const float* __restrict__ relw,
                        const float* __restrict__ gamma,
                        const float* __restrict__ beta) {
    int b = blockIdx.x, tid = threadIdx.x;
    if (b < N_RELS) {
        __shared__ float rr[D];
        if (tid < 128) rr[tid] = g_r0[b * D + tid];
        __syncthreads();
        if (tid >= 128) return;
        float acc = 0.f;
#pragma unroll 16
        for (int d = 0; d < D; ++d) acc += rr[d] * relw[d * D + tid];
        g_r1[b * D + tid] = acc;
        g_rh[b * D + tid] = __float2half(acc);
        return;
    }
    __shared__ float s_scale[D], s_shift[D];
    if (tid < D) {
        float inv_n = 1.0f / (float)N_ENT;
        float mean = g_sums[tid] * inv_n;
        float var = fmaxf(g_sumsq[tid] * inv_n - mean * mean, 0.f);
        float rs = rsqrtf(var + BN_EPS);
        float sc = rs * gamma[tid];
        s_scale[tid] = sc;
        s_shift[tid] = beta[tid] - mean * sc;
    }
    __syncthreads();
    int base = (b - N_RELS) * 4096;
#pragma unroll
    for (int j = 0; j < 16; ++j) {
        int i = base + tid + j * 256;
        if (i >= N_ENT * D / 4) break;
        int c4 = (i & 31) * 4;
        uint2 v = reinterpret_cast<const uint2*>(g_X1h)[i];
        float2 v01 = __half22float2(*reinterpret_cast<__half2*>(&v.x));
        float2 v23 = __half22float2(*reinterpret_cast<__half2*>(&v.y));
        float x = tanhf(v01.x * s_scale[c4 + 0] + s_shift[c4 + 0]);
        float y = tanhf(v01.y * s_scale[c4 + 1] + s_shift[c4 + 1]);
        float z = tanhf(v23.x * s_scale[c4 + 2] + s_shift[c4 + 2]);
        float w = tanhf(v23.y * s_scale[c4 + 3] + s_shift[c4 + 3]);
        reinterpret_cast<uint2*>(g_xh)[i] = make_uint2(pkh(x, y), pkh(z, w));
    }
}

// ====== scoring: inline r2 = r1 @ relw2, BN+tanh of X2h, L1 distance ========
__global__ void k_score(const int* __restrict__ trip,
                        const float* __restrict__ relw2,
                        const float* __restrict__ gamma,
                        const float* __restrict__ beta,
                        float* __restrict__ out) {
    __shared__ float s_scale[D], s_shift[D];
    int tid = threadIdx.x;
    if (tid < D) {
        float inv_n = 1.0f / (float)N_ENT;
        float mean = g_sums[D + tid] * inv_n;
        float var = fmaxf(g_sumsq[D + tid] * inv_n - mean * mean, 0.f);
        float rs = rsqrtf(var + BN_EPS);
        float sc = rs * gamma[tid];
        s_scale[tid] = sc;
        s_shift[tid] = beta[tid] - mean * sc;
    }
    __syncthreads();
    int t = blockIdx.x * 8 + (tid >> 5);
    if (t >= N_TRIPLES_C) return;
    int lane = tid & 31;
    int h = trip[t * 3], rl = trip[t * 3 + 1], tl = trip[t * 3 + 2];
    int c4 = lane * 4;
    // inline r2 row: rv[c] = sum_d r1[rl][d] * relw2[d][c]
    float4 rv = make_float4(0.f, 0.f, 0.f, 0.f);
    const float* r1row = g_r1 + (size_t)rl * D;
#pragma unroll 8
    for (int d = 0; d < D; ++d) {
        float rd = __ldg(r1row + d);
        float4 w4 = *reinterpret_cast<const float4*>(relw2 + (size_t)d * D + c4);
        rv.x += rd * w4.x; rv.y += rd * w4.y; rv.z += rd * w4.z; rv.w += rd * w4.w;
    }
    float4 sc = *(reinterpret_cast<const float4*>(s_scale) + lane);
    float4 sh = *(reinterpret_cast<const float4*>(s_shift) + lane);
    uint2 hu = *(reinterpret_cast<const uint2*>(g_X2h + (size_t)h * D) + lane);
    uint2 tu = *(reinterpret_cast<const uint2*>(g_X2h + (size_t)tl * D) + lane);
    float2 h01 = __half22float2(*reinterpret_cast<__half2*>(&hu.x));
    float2 h23 = __half22float2(*reinterpret_cast<__half2*>(&hu.y));
    float2 t01 = __half22float2(*reinterpret_cast<__half2*>(&tu.x));
    float2 t23 = __half22float2(*reinterpret_cast<__half2*>(&tu.y));
    float hx = tanhf(h01.x * sc.x + sh.x), tx = tanhf(t01.x * sc.x + sh.x);
    float hy = tanhf(h01.y * sc.y + sh.y), ty = tanhf(t01.y * sc.y + sh.y);
    float hz = tanhf(h23.x * sc.z + sh.z), tz = tanhf(t23.x * sc.z + sh.z);
    float hw = tanhf(h23.y * sc.w + sh.w), tw = tanhf(t23.y * sc.w + sh.w);
    float p = fabsf(hx + rv.x - tx) + fabsf(hy + rv.y - ty) +
              fabsf(hz + rv.z - tz) + fabsf(hw + rv.w - tw);
#pragma unroll
    for (int o = 16; o; o >>= 1) p += __shfl_xor_sync(0xffffffffu, p, o);
    if (lane == 0) out[t] = p;
}

// ================= host side =================
static float* sym_addr_f(const void* sym) {
    void* p = nullptr;
    cudaGetSymbolAddress(&p, sym);
    return reinterpret_cast<float*>(p);
}
static __half* sym_addr_h(const void* sym) {
    void* p = nullptr;
    cudaGetSymbolAddress(&p, sym);
    return reinterpret_cast<__half*>(p);
}

extern "C" void kernel_launch(void* const* d_in, const int* in_sizes, int n_in,
                              void* d_out, int out_size) {
    (void)in_sizes; (void)n_in; (void)out_size;
    const float* entity = (const float*)d_in[0];
    const float* bases  = (const float*)d_in[1];
    const float* coeff  = (const float*)d_in[2];
    const float* selfr  = (const float*)d_in[3];
    const float* W1     = (const float*)d_in[4];
    const float* relw1  = (const float*)d_in[5];
    const float* g1     = (const float*)d_in[6];
    const float* b1     = (const float*)d_in[7];
    const float* W2     = (const float*)d_in[8];
    const float* relw2  = (const float*)d_in[9];
    const float* g2     = (const float*)d_in[10];
    const float* b2     = (const float*)d_in[11];
    const int* edge_index = (const int*)d_in[13];
    const int* edge_type  = (const int*)d_in[14];
    const int* yv         = (const int*)d_in[15];
    const int* triples    = (const int*)d_in[16];
    float* out = (float*)d_out;

    float* p_sums = sym_addr_f(g_sums);
    float* p_sumsq = sym_addr_f(g_sumsq);
    __half* p_Wh = sym_addr_h(g_Wh);
    __half* p_X1h = sym_addr_h(g_X1h);
    __half* p_X2h = sym_addr_h(g_X2h);

    cudaFuncSetAttribute(k_gemm, cudaFuncAttributeMaxDynamicSharedMemorySize, SMEM_DYN);

    // ---- prep + CSR build (11 launches total) ----
    k_prep0<<<598 + 12500, 256>>>(W1, W2, coeff, bases, selfr, entity);
    k_hist<<<(N_EDGES_C + 255) / 256, 256>>>(edge_index);
    k_scan1<<<SCAN_BLKS, 256>>>();
    k_scan3<<<(N_ENT + 255) / 256, 256>>>();
    k_perm<<<(N_EDGES_C + 255) / 256, 256>>>(edge_index, edge_type, yv);

    // ---- layer 1 ----
    k_aggr<<<N_ENT / 8, 256>>>();
    k_gemm<<<GEMM_BLKS, 256, SMEM_DYN>>>(p_X1h, p_Wh, p_sums, p_sumsq);
    k_post1<<<N_RELS + 782, 256>>>(relw1, g1, b1);

    // ---- layer 2 ----
    k_aggr<<<N_ENT / 8, 256>>>();
    k_gemm<<<GEMM_BLKS, 256, SMEM_DYN>>>(p_X2h, p_Wh + 3 * D * D, p_sums + D, p_sumsq + D);

    // ---- scoring (inline r2 + layer-2 BN+tanh) ----
    k_score<<<N_TRIPLES_C / 8, 256>>>(triples, relw2, g2, b2, out);
}

// round 13
// speedup vs baseline: 1.0569x; 1.0569x over previous
#include <cuda_runtime.h>
#include <cuda_fp16.h>
#include <cstdint>
#include <cstddef>

// ---------------- problem constants ----------------
#define N_ENT      100000
#define N_RELS     401
#define N_BASES    50
#define D          128
#define N_EDGES_C  800000
#define N_TRIPLES_C 4096
#define BN_EPS     1e-5f
#define SCAN_BLKS  98             // 98 * 1024 >= 100000

// ---------------- scratch ----------------
__device__ float g_r0[N_RELS * D];
__device__ float g_r1[N_RELS * D];
__device__ float g_r2[N_RELS * D];
__device__ __half g_rh[N_RELS * D];                    // fp16 gather copy of current r
__device__ __half g_xh[(size_t)N_ENT * D];             // fp16 gather table (25.6 MB)
__device__ __half g_agg3h[(size_t)3 * N_ENT * D];      // per-class aggregates, fp16 (76.8 MB)
__device__ __half g_X1h[(size_t)N_ENT * D];            // layer-1 pre-BN output (fp16)
__device__ __half g_X2h[(size_t)N_ENT * D];            // layer-2 pre-BN output (fp16)
__device__ float g_sums[2 * D];
__device__ float g_sumsq[2 * D];
__device__ __half g_Wh[6 * D * D];                     // fp16 W1[0..2], W2[0..2]
// CSR
__device__ int g_deg[N_ENT];
__device__ int g_rs[N_ENT];
__device__ int g_cur[N_ENT];
__device__ int g_bsum[SCAN_BLKS];
__device__ int2 g_edge[N_EDGES_C];     // (src, et | y<<16)

// ---------------- helpers ----------------
__device__ __forceinline__ uint32_t smem_u32(const void* p) {
    uint32_t a;
    asm("{ .reg .u64 t; cvta.to.shared.u64 t, %1; cvt.u32.u64 %0, t; }" : "=r"(a) : "l"(p));
    return a;
}
__device__ __forceinline__ uint32_t pkh(float a, float b) {
    __half2 t = __floats2half2_rn(a, b);
    return *reinterpret_cast<uint32_t*>(&t);
}
__device__ __forceinline__ void ldsm_x4(uint32_t* r, uint32_t addr) {
    asm volatile("ldmatrix.sync.aligned.m8n8.x4.shared.b16 {%0,%1,%2,%3}, [%4];"
                 : "=r"(r[0]), "=r"(r[1]), "=r"(r[2]), "=r"(r[3]) : "r"(addr));
}
__device__ __forceinline__ void ldsm_x4_t(uint32_t* r, uint32_t addr) {
    asm volatile("ldmatrix.sync.aligned.m8n8.x4.trans.shared.b16 {%0,%1,%2,%3}, [%4];"
                 : "=r"(r[0]), "=r"(r[1]), "=r"(r[2]), "=r"(r[3]) : "r"(addr));
}
__device__ __forceinline__ void mma16816(float* c, const uint32_t* a, const uint32_t* b) {
    asm volatile(
        "mma.sync.aligned.m16n8k16.row.col.f32.f16.f16.f32 "
        "{%0,%1,%2,%3}, {%4,%5,%6,%7}, {%8,%9}, {%0,%1,%2,%3};"
        : "+f"(c[0]), "+f"(c[1]), "+f"(c[2]), "+f"(c[3])
        : "r"(a[0]), "r"(a[1]), "r"(a[2]), "r"(a[3]), "r"(b[0]), "r"(b[1]));
}
__device__ __forceinline__ void acc4(float4& a, const uint2& xv, const uint2& rv) {
    float2 x01 = __half22float2(*reinterpret_cast<const __half2*>(&xv.x));
    float2 x23 = __half22float2(*reinterpret_cast<const __half2*>(&xv.y));
    float2 r01 = __half22float2(*reinterpret_cast<const __half2*>(&rv.x));
    float2 r23 = __half22float2(*reinterpret_cast<const __half2*>(&rv.y));
    a.x += x01.x - r01.x; a.y += x01.y - r01.y;
    a.z += x23.x - r23.x; a.w += x23.y - r23.y;
}

// ================= r0 (fp32 + fp16) + deg-zero combined =================
__global__ void k_r0z(const float* __restrict__ coeff,
                      const float* __restrict__ bases,
                      const float* __restrict__ selfr) {
    int b = blockIdx.x;
    if (b >= 201) {
        int i = (b - 201) * 256 + threadIdx.x;
        if (i < N_ENT) g_deg[i] = 0;
        return;
    }
    int c = threadIdx.x;
    if (c >= 128) return;
    if (b == 200) {
        float v = selfr[c];
        g_r0[400 * D + c] = v;
        g_rh[400 * D + c] = __float2half(v);
        return;
    }
    __shared__ float co[N_BASES];
    if (c < N_BASES) co[c] = coeff[b * N_BASES + c];
    __syncthreads();
    float acc = 0.f;
#pragma unroll
    for (int i = 0; i < N_BASES; ++i) acc += co[i] * bases[i * D + c];
    g_r0[b * D + c] = acc;
    g_r0[(200 + b) * D + c] = -acc;
    g_rh[b * D + c] = __float2half(acc);
    g_rh[(200 + b) * D + c] = __float2half(-acc);
}

// ================= prep: W fp16 (both layers) + stats zero + entity fp16 =====
__global__ void k_prep(const float* __restrict__ W1,
                       const float* __restrict__ W2,
                       const float* __restrict__ entity) {
    int b = blockIdx.x;
    if (b < 6) {
        if (b == 0 && threadIdx.x < 256) {
            g_sums[threadIdx.x] = 0.f;
            g_sumsq[threadIdx.x] = 0.f;
        }
        const float* W = (b < 3) ? (W1 + b * D * D) : (W2 + (b - 3) * D * D);
        for (int idx = threadIdx.x; idx < D * D; idx += blockDim.x)
            g_Wh[b * D * D + idx] = __float2half(W[idx]);
        return;
    }
    int i = (b - 6) * 256 + threadIdx.x;
    if (i < N_ENT * D / 4) {
        float4 v = reinterpret_cast<const float4*>(entity)[i];
        reinterpret_cast<uint2*>(g_xh)[i] = make_uint2(pkh(v.x, v.y), pkh(v.z, v.w));
    }
}

// ================= CSR build =================
__global__ void k_hist(const int* __restrict__ ei) {
    int e = blockIdx.x * blockDim.x + threadIdx.x;
    if (e < N_EDGES_C) atomicAdd(&g_deg[ei[N_EDGES_C + e]], 1);
}
__global__ void k_scan1() {
    __shared__ int ts[256];
    int b = blockIdx.x, t = threadIdx.x;
    int base = b * 1024 + t * 4;
    int v[4];
#pragma unroll
    for (int j = 0; j < 4; ++j)
        v[j] = (base + j < N_ENT) ? g_deg[base + j] : 0;
    int s = v[0] + v[1] + v[2] + v[3];
    ts[t] = s;
    __syncthreads();
    for (int off = 1; off < 256; off <<= 1) {
        int x = (t >= off) ? ts[t - off] : 0;
        __syncthreads();
        ts[t] += x;
        __syncthreads();
    }
    int excl = ts[t] - s;
    if (t == 255) g_bsum[b] = ts[255];
#pragma unroll
    for (int j = 0; j < 4; ++j) {
        if (base + j < N_ENT) g_rs[base + j] = excl;
        excl += v[j];
    }
}
__global__ void k_scan3() {
    __shared__ int ts[128];
    __shared__ int s_pref[128];
    int t = threadIdx.x;
    int v0 = 0;
    if (t < 128) {
        v0 = (t < SCAN_BLKS) ? g_bsum[t] : 0;
        ts[t] = v0;
    }
    __syncthreads();
    for (int off = 1; off < 128; off <<= 1) {
        int x = (t >= off && t < 128) ? ts[t - off] : 0;
        __syncthreads();
        if (t < 128) ts[t] += x;
        __syncthreads();
    }
    if (t < 128) s_pref[t] = ts[t] - v0;
    __syncthreads();
    int i = blockIdx.x * 256 + t;
    if (i < N_ENT) {
        int v = g_rs[i] + s_pref[i >> 10];
        g_rs[i] = v;
        g_cur[i] = v;
    }
}
__global__ void k_perm(const int* __restrict__ ei,
                       const int* __restrict__ et,
                       const int* __restrict__ yv) {
    int e = blockIdx.x * blockDim.x + threadIdx.x;
    if (e >= N_EDGES_C) return;
    int dst = ei[N_EDGES_C + e];
    int pos = atomicAdd(&g_cur[dst], 1);
    g_edge[pos] = make_int2(ei[e], et[e] | (yv[e] << 16));
}

// ================= per-dst aggregation (fp16 gather -> fp16 agg3) ===========
__global__ __launch_bounds__(256) void k_aggr() {
    int d = blockIdx.x * 8 + (threadIdx.x >> 5);
    if (d >= N_ENT) return;
    int lane = threadIdx.x & 31;
    int start = g_rs[d];
    int end = start + g_deg[d];
    float4 a0 = make_float4(0.f, 0.f, 0.f, 0.f), a1 = a0, a2 = a0;
    int i = start;
    for (; i + 1 < end; i += 2) {
        int2 e0 = __ldg(&g_edge[i]);
        int2 e1 = __ldg(&g_edge[i + 1]);
        uint2 x0 = __ldg(reinterpret_cast<const uint2*>(g_xh + (size_t)e0.x * D) + lane);
        uint2 x1 = __ldg(reinterpret_cast<const uint2*>(g_xh + (size_t)e1.x * D) + lane);
        uint2 r0v = __ldg(reinterpret_cast<const uint2*>(g_rh + (size_t)(e0.y & 0xFFFF) * D) + lane);
        uint2 r1v = __ldg(reinterpret_cast<const uint2*>(g_rh + (size_t)(e1.y & 0xFFFF) * D) + lane);
        int y0 = e0.y >> 16, y1 = e1.y >> 16;
        if (y0 == 0) acc4(a0, x0, r0v); else if (y0 == 1) acc4(a1, x0, r0v); else acc4(a2, x0, r0v);
        if (y1 == 0) acc4(a0, x1, r1v); else if (y1 == 1) acc4(a1, x1, r1v); else acc4(a2, x1, r1v);
    }
    if (i < end) {
        int2 e0 = __ldg(&g_edge[i]);
        uint2 x0 = __ldg(reinterpret_cast<const uint2*>(g_xh + (size_t)e0.x * D) + lane);
        uint2 r0v = __ldg(reinterpret_cast<const uint2*>(g_rh + (size_t)(e0.y & 0xFFFF) * D) + lane);
        int y0 = e0.y >> 16;
        if (y0 == 0) acc4(a0, x0, r0v); else if (y0 == 1) acc4(a1, x0, r0v); else acc4(a2, x0, r0v);
    }
    uint2* o0 = reinterpret_cast<uint2*>(g_agg3h + (size_t)d * D) + lane;
    uint2* o1 = reinterpret_cast<uint2*>(g_agg3h + ((size_t)N_ENT + d) * D) + lane;
    uint2* o2 = reinterpret_cast<uint2*>(g_agg3h + ((size_t)2 * N_ENT + d) * D) + lane;
    *o0 = make_uint2(pkh(a0.x, a0.y), pkh(a0.z, a0.w));
    *o1 = make_uint2(pkh(a1.x, a1.y), pkh(a1.z, a1.w));
    *o2 = make_uint2(pkh(a2.x, a2.y), pkh(a2.z, a2.w));
}

// ================= relation GEMV (no finalize; overlappable with GEMM) =======
__global__ void k_relgemv(const float* __restrict__ rin,
                          const float* __restrict__ relw,
                          float* __restrict__ rout,
                          __half* __restrict__ routh) {
    int t = blockIdx.x, c = threadIdx.x;
    __shared__ float rr[D];
    rr[c] = rin[t * D + c];
    __syncthreads();
    float acc = 0.f;
#pragma unroll 16
    for (int d = 0; d < D; ++d) acc += rr[d] * relw[d * D + c];
    rout[t * D + c] = acc;
    if (routh) routh[t * D + c] = __float2half(acc);
}

// ============ GEMM: out = sum_k agg3h[k] @ W[k], fused BN stats, fp16 out ====
#define AP 136
#define A_TILE_B (64 * AP * 2)          // 17408
#define W_TILE_B (128 * AP * 2)         // 34816
#define SMEM_DYN (A_TILE_B + W_TILE_B)  // 52224
#define GEMM_BLKS 1563                  // ceil(100000/64)
__global__ __launch_bounds__(256, 4) void k_gemm(__half* __restrict__ outp,
                                                 const __half* __restrict__ Wset,
                                                 float* __restrict__ sums,
                                                 float* __restrict__ sumsq) {
    extern __shared__ unsigned char sm[];
    __half* sA = reinterpret_cast<__half*>(sm);
    __half* sW = reinterpret_cast<__half*>(sm + A_TILE_B);
    __shared__ float s_sum[D], s_sq[D];

    const int tid = threadIdx.x, wid = tid >> 5, lane = tid & 31;
    const int row0 = blockIdx.x * 64;
    const int wm = wid >> 1, wn = wid & 1;
    const int mbase = wm * 16, nbase = wn * 64;

    if (tid < D) { s_sum[tid] = 0.f; s_sq[tid] = 0.f; }

    const uint32_t uA = smem_u32(sA), uW = smem_u32(sW);

    float acc[8][4];
#pragma unroll
    for (int i = 0; i < 8; ++i)
#pragma unroll
        for (int j = 0; j < 4; ++j) acc[i][j] = 0.f;

    for (int k = 0; k < 3; ++k) {
        __syncthreads();
        const uint4* gw = reinterpret_cast<const uint4*>(Wset + k * D * D);
#pragma unroll
        for (int i = 0; i < 8; ++i) {
            int idx = tid + i * 256;
            int r = idx >> 4, c8 = (idx & 15) * 8;
            *reinterpret_cast<uint4*>(sW + r * AP + c8) = gw[idx];
        }
        const __half* ga = g_agg3h + (size_t)k * N_ENT * D;
#pragma unroll
        for (int i = 0; i < 4; ++i) {
            int idx = tid + i * 256;
            int r = idx >> 4, c8 = (idx & 15) * 8;
            int grow = row0 + r;
            uint4 v = make_uint4(0u, 0u, 0u, 0u);
            if (grow < N_ENT)
                v = *reinterpret_cast<const uint4*>(ga + (size_t)grow * D + c8);
            *reinterpret_cast<uint4*>(sA + r * AP + c8) = v;
        }
        __syncthreads();

#pragma unroll
        for (int ks = 0; ks < 8; ++ks) {
            const int k0 = ks * 16;
            uint32_t ah[4];
            {
                int row = mbase + (lane & 15);
                int col = k0 + (lane >> 4) * 8;
                ldsm_x4(ah, uA + (uint32_t)(row * AP + col) * 2);
            }
            uint32_t bh[8][2];
#pragma unroll
            for (int p = 0; p < 4; ++p) {
                int row = k0 + ((lane >> 3) & 1) * 8 + (lane & 7);
                int col = nbase + p * 16 + (lane >> 4) * 8;
                uint32_t t4[4];
                ldsm_x4_t(t4, uW + (uint32_t)(row * AP + col) * 2);
                bh[2 * p][0] = t4[0]; bh[2 * p][1] = t4[1];
                bh[2 * p + 1][0] = t4[2]; bh[2 * p + 1][1] = t4[3];
            }
#pragma unroll
            for (int nt = 0; nt < 8; ++nt)
                mma16816(acc[nt], ah, bh[nt]);
        }
    }

    const int g = lane >> 2, t2 = (lane & 3) * 2;
    int r0 = row0 + mbase + g;
    int r1 = r0 + 8;
    bool ok0 = r0 < N_ENT, ok1 = r1 < N_ENT;
#pragma unroll
    for (int nt = 0; nt < 8; ++nt) {
        int col = nbase + nt * 8 + t2;
        if (ok0)
            *reinterpret_cast<uint32_t*>(outp + (size_t)r0 * D + col) =
                pkh(acc[nt][0], acc[nt][1]);
        if (ok1)
            *reinterpret_cast<uint32_t*>(outp + (size_t)r1 * D + col) =
                pkh(acc[nt][2], acc[nt][3]);
        float a0 = ok0 ? acc[nt][0] : 0.f, a1 = ok0 ? acc[nt][1] : 0.f;
        float a2 = ok1 ? acc[nt][2] : 0.f, a3 = ok1 ? acc[nt][3] : 0.f;
        float se = a0 + a2, so = a1 + a3;
        float qe = a0 * a0 + a2 * a2, qo = a1 * a1 + a3 * a3;
#pragma unroll
        for (int off = 16; off >= 4; off >>= 1) {
            se += __shfl_down_sync(0xffffffffu, se, off);
            so += __shfl_down_sync(0xffffffffu, so, off);
            qe += __shfl_down_sync(0xffffffffu, qe, off);
            qo += __shfl_down_sync(0xffffffffu, qo, off);
        }
        if (lane < 4) {
            atomicAdd(&s_sum[col], se);
            atomicAdd(&s_sum[col + 1], so);
            atomicAdd(&s_sq[col], qe);
            atomicAdd(&s_sq[col + 1], qo);
        }
    }
    __syncthreads();
    if (tid < D) {
        atomicAdd(&sums[tid], s_sum[tid]);
        atomicAdd(&sumsq[tid], s_sq[tid]);
    }
}

// ======== bn+tanh with local finalize: X1h (pre-BN fp16) -> g_xh =============
__global__ void k_bntanh(const __half* __restrict__ xin,
                         const float* __restrict__ gamma,
                         const float* __restrict__ beta) {
    __shared__ float s_scale[D], s_shift[D];
    int tid = threadIdx.x;
    if (tid < D) {
        float inv_n = 1.0f / (float)N_ENT;
        float mean = g_sums[tid] * inv_n;
        float var = fmaxf(g_sumsq[tid] * inv_n - mean * mean, 0.f);
        float rs = rsqrtf(var + BN_EPS);
        float sc = rs * gamma[tid];
        s_scale[tid] = sc;
        s_shift[tid] = beta[tid] - mean * sc;
    }
    __syncthreads();
    int base = blockIdx.x * 4096;
#pragma unroll
    for (int j = 0; j < 16; ++j) {
        int i = base + tid + j * 256;
        if (i >= N_ENT * D / 4) break;
        int c4 = (i & 31) * 4;
        uint2 v = reinterpret_cast<const uint2*>(xin)[i];
        float2 v01 = __half22float2(*reinterpret_cast<__half2*>(&v.x));
        float2 v23 = __half22float2(*reinterpret_cast<__half2*>(&v.y));
        float x = tanhf(v01.x * s_scale[c4 + 0] + s_shift[c4 + 0]);
        float y = tanhf(v01.y * s_scale[c4 + 1] + s_shift[c4 + 1]);
        float z = tanhf(v23.x * s_scale[c4 + 2] + s_shift[c4 + 2]);
        float w = tanhf(v23.y * s_scale[c4 + 3] + s_shift[c4 + 3]);
        reinterpret_cast<uint2*>(g_xh)[i] = make_uint2(pkh(x, y), pkh(z, w));
    }
}

// ========= scoring: local layer-2 finalize, BN+tanh of X2h, L1 dist ==========
__global__ void k_score(const int* __restrict__ trip,
                        const float* __restrict__ gamma,
                        const float* __restrict__ beta,
                        float* __restrict__ out) {
    __shared__ float s_scale[D], s_shift[D];
    int tid = threadIdx.x;
    if (tid < D) {
        float inv_n = 1.0f / (float)N_ENT;
        float mean = g_sums[D + tid] * inv_n;
        float var = fmaxf(g_sumsq[D + tid] * inv_n - mean * mean, 0.f);
        float rs = rsqrtf(var + BN_EPS);
        float sc = rs * gamma[tid];
        s_scale[tid] = sc;
        s_shift[tid] = beta[tid] - mean * sc;
    }
    __syncthreads();
    int t = blockIdx.x * 8 + (tid >> 5);
    if (t >= N_TRIPLES_C) return;
    int lane = tid & 31;
    int h = trip[t * 3], rl = trip[t * 3 + 1], tl = trip[t * 3 + 2];
    float4 sc = *(reinterpret_cast<const float4*>(s_scale) + lane);
    float4 sh = *(reinterpret_cast<const float4*>(s_shift) + lane);
    uint2 hu = *(reinterpret_cast<const uint2*>(g_X2h + (size_t)h * D) + lane);
    uint2 tu = *(reinterpret_cast<const uint2*>(g_X2h + (size_t)tl * D) + lane);
    float4 rv = *(reinterpret_cast<const float4*>(g_r2 + (size_t)rl * D) + lane);
    float2 h01 = __half22float2(*reinterpret_cast<__half2*>(&hu.x));
    float2 h23 = __half22float2(*reinterpret_cast<__half2*>(&hu.y));
    float2 t01 = __half22float2(*reinterpret_cast<__half2*>(&tu.x));
    float2 t23 = __half22float2(*reinterpret_cast<__half2*>(&tu.y));
    float hx = tanhf(h01.x * sc.x + sh.x), tx = tanhf(t01.x * sc.x + sh.x);
    float hy = tanhf(h01.y * sc.y + sh.y), ty = tanhf(t01.y * sc.y + sh.y);
    float hz = tanhf(h23.x * sc.z + sh.z), tz = tanhf(t23.x * sc.z + sh.z);
    float hw = tanhf(h23.y * sc.w + sh.w), tw = tanhf(t23.y * sc.w + sh.w);
    float p = fabsf(hx + rv.x - tx) + fabsf(hy + rv.y - ty) +
              fabsf(hz + rv.z - tz) + fabsf(hw + rv.w - tw);
#pragma unroll
    for (int o = 16; o; o >>= 1) p += __shfl_xor_sync(0xffffffffu, p, o);
    if (lane == 0) out[t] = p;
}

// ================= host side =================
static float* sym_addr_f(const void* sym) {
    void* p = nullptr;
    cudaGetSymbolAddress(&p, sym);
    return reinterpret_cast<float*>(p);
}
static __half* sym_addr_h(const void* sym) {
    void* p = nullptr;
    cudaGetSymbolAddress(&p, sym);
    return reinterpret_cast<__half*>(p);
}

extern "C" void kernel_launch(void* const* d_in, const int* in_sizes, int n_in,
                              void* d_out, int out_size) {
    (void)in_sizes; (void)n_in; (void)out_size;
    const float* entity = (const float*)d_in[0];
    const float* bases  = (const float*)d_in[1];
    const float* coeff  = (const float*)d_in[2];
    const float* selfr  = (const float*)d_in[3];
    const float* W1     = (const float*)d_in[4];
    const float* relw1  = (const float*)d_in[5];
    const float* g1     = (const float*)d_in[6];
    const float* b1     = (const float*)d_in[7];
    const float* W2     = (const float*)d_in[8];
    const float* relw2  = (const float*)d_in[9];
    const float* g2     = (const float*)d_in[10];
    const float* b2     = (const float*)d_in[11];
    const int* edge_index = (const int*)d_in[13];
    const int* edge_type  = (const int*)d_in[14];
    const int* yv         = (const int*)d_in[15];
    const int* triples    = (const int*)d_in[16];
    float* out = (float*)d_out;

    float* p_r0 = sym_addr_f(g_r0);
    float* p_r1 = sym_addr_f(g_r1);
    float* p_r2 = sym_addr_f(g_r2);
    float* p_sums = sym_addr_f(g_sums);
    float* p_sumsq = sym_addr_f(g_sumsq);
    __half* p_rh = sym_addr_h(g_rh);
    __half* p_Wh = sym_addr_h(g_Wh);
    __half* p_X1h = sym_addr_h(g_X1h);
    __half* p_X2h = sym_addr_h(g_X2h);

    // lazy-create side stream + events (host objects only; first call is the
    // non-captured correctness run, so creation is outside graph capture)
    static cudaStream_t sA = nullptr;
    static cudaEvent_t evFork = nullptr, evPrep = nullptr,
                       evA1 = nullptr, evRel1 = nullptr,
                       evA2 = nullptr, evRel2 = nullptr;
    if (!sA) {
        cudaStreamCreateWithFlags(&sA, cudaStreamNonBlocking);
        cudaEventCreateWithFlags(&evFork, cudaEventDisableTiming);
        cudaEventCreateWithFlags(&evPrep, cudaEventDisableTiming);
        cudaEventCreateWithFlags(&evA1, cudaEventDisableTiming);
        cudaEventCreateWithFlags(&evRel1, cudaEventDisableTiming);
        cudaEventCreateWithFlags(&evA2, cudaEventDisableTiming);
        cudaEventCreateWithFlags(&evRel2, cudaEventDisableTiming);
    }

    cudaFuncSetAttribute(k_gemm, cudaFuncAttributeMaxDynamicSharedMemorySize, SMEM_DYN);

    // ---- r0 + deg zero (needed by CSR hist) ----
    k_r0z<<<201 + (N_ENT + 255) / 256, 256>>>(coeff, bases, selfr);

    // fork: prep (W + entity fp16 + stats zero) runs concurrent with CSR build
    cudaEventRecord(evFork, 0);
    cudaStreamWaitEvent(sA, evFork, 0);
    k_prep<<<6 + (N_ENT * D / 4 + 255) / 256, 256, 0, sA>>>(W1, W2, entity);
    cudaEventRecord(evPrep, sA);

    k_hist<<<(N_EDGES_C + 255) / 256, 256>>>(edge_index);
    k_scan1<<<SCAN_BLKS, 256>>>();
    k_scan3<<<(N_ENT + 255) / 256, 256>>>();
    k_perm<<<(N_EDGES_C + 255) / 256, 256>>>(edge_index, edge_type, yv);
    cudaStreamWaitEvent(0, evPrep, 0);           // join before aggregation

    // ---- layer 1 ----
    k_aggr<<<N_ENT / 8, 256>>>();
    cudaEventRecord(evA1, 0);
    cudaStreamWaitEvent(sA, evA1, 0);            // rel1 overwrites g_rh: wait aggr1
    k_relgemv<<<N_RELS, 128, 0, sA>>>(p_r0, relw1, p_r1, p_rh);
    cudaEventRecord(evRel1, sA);
    k_gemm<<<GEMM_BLKS, 256, SMEM_DYN>>>(p_X1h, p_Wh, p_sums, p_sumsq);
    k_bntanh<<<782, 256>>>(p_X1h, g1, b1);       // local finalize; writes g_xh
    cudaStreamWaitEvent(0, evRel1, 0);           // aggr2 reads new g_rh

    // ---- layer 2 ----
    k_aggr<<<N_ENT / 8, 256>>>();
    cudaEventRecord(evA2, 0);
    cudaStreamWaitEvent(sA, evA2, 0);
    k_relgemv<<<N_RELS, 128, 0, sA>>>(p_r1, relw2, p_r2, nullptr);
    cudaEventRecord(evRel2, sA);
    k_gemm<<<GEMM_BLKS, 256, SMEM_DYN>>>(p_X2h, p_Wh + 3 * D * D, p_sums + D, p_sumsq + D);
    cudaStreamWaitEvent(0, evRel2, 0);           // score reads g_r2

    // ---- scoring (local layer-2 finalize inside) ----
    k_score<<<N_TRIPLES_C / 8, 256>>>(triples, g2, b2, out);
}

// round 15
// speedup vs baseline: 1.0837x; 1.0254x over previous
#include <cuda_runtime.h>
#include <cuda_fp16.h>
#include <cstdint>
#include <cstddef>

// ---------------- problem constants ----------------
#define N_ENT      100000
#define N_RELS     401
#define N_BASES    50
#define D          128
#define N_EDGES_C  800000
#define N_TRIPLES_C 4096
#define BN_EPS     1e-5f
#define SCAN_BLKS  98             // 98 * 1024 >= 100000

// ---------------- scratch ----------------
__device__ float g_r0[N_RELS * D];
__device__ float g_r1[N_RELS * D];
__device__ float g_r2[N_RELS * D];
__device__ __half g_rh[N_RELS * D];                    // fp16 gather copy of current r
__device__ __half g_xh[(size_t)N_ENT * D];             // fp16 gather table (25.6 MB)
__device__ __half g_agg3h[(size_t)3 * N_ENT * D];      // per-class aggregates, fp16 (76.8 MB)
__device__ __half g_X1h[(size_t)N_ENT * D];            // layer-1 pre-BN output (fp16)
__device__ __half g_X2h[(size_t)N_ENT * D];            // layer-2 pre-BN output (fp16)
__device__ float g_sums[2 * D];
__device__ float g_sumsq[2 * D];
__device__ __half g_Wh[6 * D * D];                     // fp16 W1[0..2], W2[0..2]
// CSR
__device__ int g_deg[N_ENT];
__device__ int g_rs[N_ENT];
__device__ int g_cur[N_ENT];
__device__ int g_bsum[SCAN_BLKS];
__device__ int2 g_edge[N_EDGES_C];     // (src, et | y<<16)

// ---------------- helpers ----------------
__device__ __forceinline__ uint32_t smem_u32(const void* p) {
    uint32_t a;
    asm("{ .reg .u64 t; cvta.to.shared.u64 t, %1; cvt.u32.u64 %0, t; }" : "=r"(a) : "l"(p));
    return a;
}
__device__ __forceinline__ uint32_t pkh(float a, float b) {
    __half2 t = __floats2half2_rn(a, b);
    return *reinterpret_cast<uint32_t*>(&t);
}
__device__ __forceinline__ void ldsm_x4(uint32_t* r, uint32_t addr) {
    asm volatile("ldmatrix.sync.aligned.m8n8.x4.shared.b16 {%0,%1,%2,%3}, [%4];"
                 : "=r"(r[0]), "=r"(r[1]), "=r"(r[2]), "=r"(r[3]) : "r"(addr));
}
__device__ __forceinline__ void ldsm_x4_t(uint32_t* r, uint32_t addr) {
    asm volatile("ldmatrix.sync.aligned.m8n8.x4.trans.shared.b16 {%0,%1,%2,%3}, [%4];"
                 : "=r"(r[0]), "=r"(r[1]), "=r"(r[2]), "=r"(r[3]) : "r"(addr));
}
__device__ __forceinline__ void mma16816(float* c, const uint32_t* a, const uint32_t* b) {
    asm volatile(
        "mma.sync.aligned.m16n8k16.row.col.f32.f16.f16.f32 "
        "{%0,%1,%2,%3}, {%4,%5,%6,%7}, {%8,%9}, {%0,%1,%2,%3};"
        : "+f"(c[0]), "+f"(c[1]), "+f"(c[2]), "+f"(c[3])
        : "r"(a[0]), "r"(a[1]), "r"(a[2]), "r"(a[3]), "r"(b[0]), "r"(b[1]));
}
__device__ __forceinline__ void acc4(float4& a, const uint2& xv, const uint2& rv) {
    float2 x01 = __half22float2(*reinterpret_cast<const __half2*>(&xv.x));
    float2 x23 = __half22float2(*reinterpret_cast<const __half2*>(&xv.y));
    float2 r01 = __half22float2(*reinterpret_cast<const __half2*>(&rv.x));
    float2 r23 = __half22float2(*reinterpret_cast<const __half2*>(&rv.y));
    a.x += x01.x - r01.x; a.y += x01.y - r01.y;
    a.z += x23.x - r23.x; a.w += x23.y - r23.y;
}

// ================= r0 (fp32 + fp16) + deg-zero combined =================
__global__ void k_r0z(const float* __restrict__ coeff,
                      const float* __restrict__ bases,
                      const float* __restrict__ selfr) {
    int b = blockIdx.x;
    if (b >= 201) {
        int i = (b - 201) * 256 + threadIdx.x;
        if (i < N_ENT) g_deg[i] = 0;
        return;
    }
    int c = threadIdx.x;
    if (c >= 128) return;
    if (b == 200) {
        float v = selfr[c];
        g_r0[400 * D + c] = v;
        g_rh[400 * D + c] = __float2half(v);
        return;
    }
    __shared__ float co[N_BASES];
    if (c < N_BASES) co[c] = coeff[b * N_BASES + c];
    __syncthreads();
    float acc = 0.f;
#pragma unroll
    for (int i = 0; i < N_BASES; ++i) acc += co[i] * bases[i * D + c];
    g_r0[b * D + c] = acc;
    g_r0[(200 + b) * D + c] = -acc;
    g_rh[b * D + c] = __float2half(acc);
    g_rh[(200 + b) * D + c] = __float2half(-acc);
}

// ================= prep: W fp16 (both layers) + stats zero + entity fp16 =====
__global__ void k_prep(const float* __restrict__ W1,
                       const float* __restrict__ W2,
                       const float* __restrict__ entity) {
    int b = blockIdx.x;
    if (b < 6) {
        if (b == 0 && threadIdx.x < 256) {
            g_sums[threadIdx.x] = 0.f;
            g_sumsq[threadIdx.x] = 0.f;
        }
        const float* W = (b < 3) ? (W1 + b * D * D) : (W2 + (b - 3) * D * D);
        for (int idx = threadIdx.x; idx < D * D; idx += blockDim.x)
            g_Wh[b * D * D + idx] = __float2half(W[idx]);
        return;
    }
    int i = (b - 6) * 256 + threadIdx.x;
    if (i < N_ENT * D / 4) {
        float4 v = reinterpret_cast<const float4*>(entity)[i];
        reinterpret_cast<uint2*>(g_xh)[i] = make_uint2(pkh(v.x, v.y), pkh(v.z, v.w));
    }
}

// ================= CSR build =================
__global__ void k_hist(const int* __restrict__ ei) {
    int e = blockIdx.x * blockDim.x + threadIdx.x;
    if (e < N_EDGES_C) atomicAdd(&g_deg[ei[N_EDGES_C + e]], 1);
}
__global__ void k_scan1() {
    __shared__ int ts[256];
    int b = blockIdx.x, t = threadIdx.x;
    int base = b * 1024 + t * 4;
    int v[4];
#pragma unroll
    for (int j = 0; j < 4; ++j)
        v[j] = (base + j < N_ENT) ? g_deg[base + j] : 0;
    int s = v[0] + v[1] + v[2] + v[3];
    ts[t] = s;
    __syncthreads();
    for (int off = 1; off < 256; off <<= 1) {
        int x = (t >= off) ? ts[t - off] : 0;
        __syncthreads();
        ts[t] += x;
        __syncthreads();
    }
    int excl = ts[t] - s;
    if (t == 255) g_bsum[b] = ts[255];
#pragma unroll
    for (int j = 0; j < 4; ++j) {
        if (base + j < N_ENT) g_rs[base + j] = excl;
        excl += v[j];
    }
}
__global__ void k_scan3() {
    __shared__ int ts[128];
    __shared__ int s_pref[128];
    int t = threadIdx.x;
    int v0 = 0;
    if (t < 128) {
        v0 = (t < SCAN_BLKS) ? g_bsum[t] : 0;
        ts[t] = v0;
    }
    __syncthreads();
    for (int off = 1; off < 128; off <<= 1) {
        int x = (t >= off && t < 128) ? ts[t - off] : 0;
        __syncthreads();
        if (t < 128) ts[t] += x;
        __syncthreads();
    }
    if (t < 128) s_pref[t] = ts[t] - v0;
    __syncthreads();
    int i = blockIdx.x * 256 + t;
    if (i < N_ENT) {
        int v = g_rs[i] + s_pref[i >> 10];
        g_rs[i] = v;
        g_cur[i] = v;
    }
}
__global__ void k_perm(const int* __restrict__ ei,
                       const int* __restrict__ et,
                       const int* __restrict__ yv) {
    int e = blockIdx.x * blockDim.x + threadIdx.x;
    if (e >= N_EDGES_C) return;
    int dst = ei[N_EDGES_C + e];
    int pos = atomicAdd(&g_cur[dst], 1);
    g_edge[pos] = make_int2(ei[e], et[e] | (yv[e] << 16));
}

// ====== per-dst aggregation (4-edge software pipeline, fp16 -> fp16) ========
__global__ __launch_bounds__(256) void k_aggr() {
    int d = blockIdx.x * 8 + (threadIdx.x >> 5);
    if (d >= N_ENT) return;
    int lane = threadIdx.x & 31;
    int start = g_rs[d];
    int end = start + g_deg[d];
    float4 a0 = make_float4(0.f, 0.f, 0.f, 0.f), a1 = a0, a2 = a0;
    int i = start;
    for (; i + 3 < end; i += 4) {
        int2 e0 = __ldg(&g_edge[i]);
        int2 e1 = __ldg(&g_edge[i + 1]);
        int2 e2 = __ldg(&g_edge[i + 2]);
        int2 e3 = __ldg(&g_edge[i + 3]);
        uint2 x0 = __ldg(reinterpret_cast<const uint2*>(g_xh + (size_t)e0.x * D) + lane);
        uint2 x1 = __ldg(reinterpret_cast<const uint2*>(g_xh + (size_t)e1.x * D) + lane);
        uint2 x2 = __ldg(reinterpret_cast<const uint2*>(g_xh + (size_t)e2.x * D) + lane);
        uint2 x3 = __ldg(reinterpret_cast<const uint2*>(g_xh + (size_t)e3.x * D) + lane);
        uint2 r0v = __ldg(reinterpret_cast<const uint2*>(g_rh + (size_t)(e0.y & 0xFFFF) * D) + lane);
        uint2 r1v = __ldg(reinterpret_cast<const uint2*>(g_rh + (size_t)(e1.y & 0xFFFF) * D) + lane);
        uint2 r2v = __ldg(reinterpret_cast<const uint2*>(g_rh + (size_t)(e2.y & 0xFFFF) * D) + lane);
        uint2 r3v = __ldg(reinterpret_cast<const uint2*>(g_rh + (size_t)(e3.y & 0xFFFF) * D) + lane);
        int y0 = e0.y >> 16, y1 = e1.y >> 16, y2 = e2.y >> 16, y3 = e3.y >> 16;
        if (y0 == 0) acc4(a0, x0, r0v); else if (y0 == 1) acc4(a1, x0, r0v); else acc4(a2, x0, r0v);
        if (y1 == 0) acc4(a0, x1, r1v); else if (y1 == 1) acc4(a1, x1, r1v); else acc4(a2, x1, r1v);
        if (y2 == 0) acc4(a0, x2, r2v); else if (y2 == 1) acc4(a1, x2, r2v); else acc4(a2, x2, r2v);
        if (y3 == 0) acc4(a0, x3, r3v); else if (y3 == 1) acc4(a1, x3, r3v); else acc4(a2, x3, r3v);
    }
    for (; i < end; ++i) {
        int2 e0 = __ldg(&g_edge[i]);
        uint2 x0 = __ldg(reinterpret_cast<const uint2*>(g_xh + (size_t)e0.x * D) + lane);
        uint2 r0v = __ldg(reinterpret_cast<const uint2*>(g_rh + (size_t)(e0.y & 0xFFFF) * D) + lane);
        int y0 = e0.y >> 16;
        if (y0 == 0) acc4(a0, x0, r0v); else if (y0 == 1) acc4(a1, x0, r0v); else acc4(a2, x0, r0v);
    }
    uint2* o0 = reinterpret_cast<uint2*>(g_agg3h + (size_t)d * D) + lane;
    uint2* o1 = reinterpret_cast<uint2*>(g_agg3h + ((size_t)N_ENT + d) * D) + lane;
    uint2* o2 = reinterpret_cast<uint2*>(g_agg3h + ((size_t)2 * N_ENT + d) * D) + lane;
    *o0 = make_uint2(pkh(a0.x, a0.y), pkh(a0.z, a0.w));
    *o1 = make_uint2(pkh(a1.x, a1.y), pkh(a1.z, a1.w));
    *o2 = make_uint2(pkh(a2.x, a2.y), pkh(a2.z, a2.w));
}

// ================= relation GEMV (no finalize; overlappable with GEMM) =======
__global__ void k_relgemv(const float* __restrict__ rin,
                          const float* __restrict__ relw,
                          float* __restrict__ rout,
                          __half* __restrict__ routh) {
    int t = blockIdx.x, c = threadIdx.x;
    __shared__ float rr[D];
    rr[c] = rin[t * D + c];
    __syncthreads();
    float acc = 0.f;
#pragma unroll 16
    for (int d = 0; d < D; ++d) acc += rr[d] * relw[d * D + c];
    rout[t * D + c] = acc;
    if (routh) routh[t * D + c] = __float2half(acc);
}

// ==== GEMM: 4-warp CTA, warp tile 32x64; out = sum_k agg3h[k]@W[k] + stats ===
#define AP 136
#define A_TILE_B (64 * AP * 2)          // 17408
#define W_TILE_B (128 * AP * 2)         // 34816
#define SMEM_DYN (A_TILE_B + W_TILE_B)  // 52224
#define GEMM_BLKS 1563                  // ceil(100000/64)
__global__ __launch_bounds__(128, 4) void k_gemm(__half* __restrict__ outp,
                                                 const __half* __restrict__ Wset,
                                                 float* __restrict__ sums,
                                                 float* __restrict__ sumsq) {
    extern __shared__ unsigned char sm[];
    __half* sA = reinterpret_cast<__half*>(sm);
    __half* sW = reinterpret_cast<__half*>(sm + A_TILE_B);
    __shared__ float s_sum[D], s_sq[D];

    const int tid = threadIdx.x, wid = tid >> 5, lane = tid & 31;
    const int row0 = blockIdx.x * 64;
    const int wm = wid >> 1, wn = wid & 1;      // 2x2 warp grid, warp tile 32x64
    const int mbase = wm * 32, nbase = wn * 64;

    if (tid < D) { s_sum[tid] = 0.f; s_sq[tid] = 0.f; }

    const uint32_t uA = smem_u32(sA), uW = smem_u32(sW);

    float acc[2][8][4];                          // [mt][nt][frag]
#pragma unroll
    for (int m = 0; m < 2; ++m)
#pragma unroll
        for (int i = 0; i < 8; ++i)
#pragma unroll
            for (int j = 0; j < 4; ++j) acc[m][i][j] = 0.f;

    for (int k = 0; k < 3; ++k) {
        __syncthreads();
        const uint4* gw = reinterpret_cast<const uint4*>(Wset + k * D * D);
#pragma unroll
        for (int i = 0; i < 16; ++i) {
            int idx = tid + i * 128;
            int r = idx >> 4, c8 = (idx & 15) * 8;
            *reinterpret_cast<uint4*>(sW + r * AP + c8) = gw[idx];
        }
        const __half* ga = g_agg3h + (size_t)k * N_ENT * D;
#pragma unroll
        for (int i = 0; i < 8; ++i) {
            int idx = tid + i * 128;
            int r = idx >> 4, c8 = (idx & 15) * 8;
            int grow = row0 + r;
            uint4 v = make_uint4(0u, 0u, 0u, 0u);
            if (grow < N_ENT)
                v = *reinterpret_cast<const uint4*>(ga + (size_t)grow * D + c8);
            *reinterpret_cast<uint4*>(sA + r * AP + c8) = v;
        }
        __syncthreads();

#pragma unroll
        for (int ks = 0; ks < 8; ++ks) {
            const int k0 = ks * 16;
            uint32_t ah[2][4];
#pragma unroll
            for (int mt = 0; mt < 2; ++mt) {
                int row = mbase + mt * 16 + (lane & 15);
                int col = k0 + (lane >> 4) * 8;
                ldsm_x4(ah[mt], uA + (uint32_t)(row * AP + col) * 2);
            }
            uint32_t bh[8][2];
#pragma unroll
            for (int p = 0; p < 4; ++p) {
                int row = k0 + ((lane >> 3) & 1) * 8 + (lane & 7);
                int col = nbase + p * 16 + (lane >> 4) * 8;
                uint32_t t4[4];
                ldsm_x4_t(t4, uW + (uint32_t)(row * AP + col) * 2);
                bh[2 * p][0] = t4[0]; bh[2 * p][1] = t4[1];
                bh[2 * p + 1][0] = t4[2]; bh[2 * p + 1][1] = t4[3];
            }
#pragma unroll
            for (int mt = 0; mt < 2; ++mt)
#pragma unroll
                for (int nt = 0; nt < 8; ++nt)
                    mma16816(acc[mt][nt], ah[mt], bh[nt]);
        }
    }

    const int g = lane >> 2, t2 = (lane & 3) * 2;
#pragma unroll
    for (int mt = 0; mt < 2; ++mt) {
        int r0 = row0 + mbase + mt * 16 + g;
        int r1 = r0 + 8;
        bool ok0 = r0 < N_ENT, ok1 = r1 < N_ENT;
#pragma unroll
        for (int nt = 0; nt < 8; ++nt) {
            int col = nbase + nt * 8 + t2;
            if (ok0)
                *reinterpret_cast<uint32_t*>(outp + (size_t)r0 * D + col) =
                    pkh(acc[mt][nt][0], acc[mt][nt][1]);
            if (ok1)
                *reinterpret_cast<uint32_t*>(outp + (size_t)r1 * D + col) =
                    pkh(acc[mt][nt][2], acc[mt][nt][3]);
            float a0 = ok0 ? acc[mt][nt][0] : 0.f, a1 = ok0 ? acc[mt][nt][1] : 0.f;
            float a2 = ok1 ? acc[mt][nt][2] : 0.f, a3 = ok1 ? acc[mt][nt][3] : 0.f;
            float se = a0 + a2, so = a1 + a3;
            float qe = a0 * a0 + a2 * a2, qo = a1 * a1 + a3 * a3;
#pragma unroll
            for (int off = 16; off >= 4; off >>= 1) {
                se += __shfl_down_sync(0xffffffffu, se, off);
                so += __shfl_down_sync(0xffffffffu, so, off);
                qe += __shfl_down_sync(0xffffffffu, qe, off);
                qo += __shfl_down_sync(0xffffffffu, qo, off);
            }
            if (lane < 4) {
                atomicAdd(&s_sum[col], se);
                atomicAdd(&s_sum[col + 1], so);
                atomicAdd(&s_sq[col], qe);
                atomicAdd(&s_sq[col + 1], qo);
            }
        }
    }
    __syncthreads();
    if (tid < D) {
        atomicAdd(&sums[tid], s_sum[tid]);
        atomicAdd(&sumsq[tid], s_sq[tid]);
    }
}

// ======== bn+tanh with local finalize: X1h (pre-BN fp16) -> g_xh =============
__global__ void k_bntanh(const __half* __restrict__ xin,
                         const float* __restrict__ gamma,
                         const float* __restrict__ beta) {
    __shared__ float s_scale[D], s_shift[D];
    int tid = threadIdx.x;
    if (tid < D) {
        float inv_n = 1.0f / (float)N_ENT;
        float mean = g_sums[tid] * inv_n;
        float var = fmaxf(g_sumsq[tid] * inv_n - mean * mean, 0.f);
        float rs = rsqrtf(var + BN_EPS);
        float sc = rs * gamma[tid];
        s_scale[tid] = sc;
        s_shift[tid] = beta[tid] - mean * sc;
    }
    __syncthreads();
    int base = blockIdx.x * 4096;
#pragma unroll
    for (int j = 0; j < 16; ++j) {
        int i = base + tid + j * 256;
        if (i >= N_ENT * D / 4) break;
        int c4 = (i & 31) * 4;
        uint2 v = reinterpret_cast<const uint2*>(xin)[i];
        float2 v01 = __half22float2(*reinterpret_cast<__half2*>(&v.x));
        float2 v23 = __half22float2(*reinterpret_cast<__half2*>(&v.y));
        float x = tanhf(v01.x * s_scale[c4 + 0] + s_shift[c4 + 0]);
        float y = tanhf(v01.y * s_scale[c4 + 1] + s_shift[c4 + 1]);
        float z = tanhf(v23.x * s_scale[c4 + 2] + s_shift[c4 + 2]);
        float w = tanhf(v23.y * s_scale[c4 + 3] + s_shift[c4 + 3]);
        reinterpret_cast<uint2*>(g_xh)[i] = make_uint2(pkh(x, y), pkh(z, w));
    }
}

// ========= scoring: local layer-2 finalize, BN+tanh of X2h, L1 dist ==========
__global__ void k_score(const int* __restrict__ trip,
                        const float* __restrict__ gamma,
                        const float* __restrict__ beta,
                        float* __restrict__ out) {
    __shared__ float s_scale[D], s_shift[D];
    int tid = threadIdx.x;
    if (tid < D) {
        float inv_n = 1.0f / (float)N_ENT;
        float mean = g_sums[D + tid] * inv_n;
        float var = fmaxf(g_sumsq[D + tid] * inv_n - mean * mean, 0.f);
        float rs = rsqrtf(var + BN_EPS);
        float sc = rs * gamma[tid];
        s_scale[tid] = sc;
        s_shift[tid] = beta[tid] - mean * sc;
    }
    __syncthreads();
    int t = blockIdx.x * 8 + (tid >> 5);
    if (t >= N_TRIPLES_C) return;
    int lane = tid & 31;
    int h = trip[t * 3], rl = trip[t * 3 + 1], tl = trip[t * 3 + 2];
    float4 sc = *(reinterpret_cast<const float4*>(s_scale) + lane);
    float4 sh = *(reinterpret_cast<const float4*>(s_shift) + lane);
    uint2 hu = *(reinterpret_cast<const uint2*>(g_X2h + (size_t)h * D) + lane);
    uint2 tu = *(reinterpret_cast<const uint2*>(g_X2h + (size_t)tl * D) + lane);
    float4 rv = *(reinterpret_cast<const float4*>(g_r2 + (size_t)rl * D) + lane);
    float2 h01 = __half22float2(*reinterpret_cast<__half2*>(&hu.x));
    float2 h23 = __half22float2(*reinterpret_cast<__half2*>(&hu.y));
    float2 t01 = __half22float2(*reinterpret_cast<__half2*>(&tu.x));
    float2 t23 = __half22float2(*reinterpret_cast<__half2*>(&tu.y));
    float hx = tanhf(h01.x * sc.x + sh.x), tx = tanhf(t01.x * sc.x + sh.x);
    float hy = tanhf(h01.y * sc.y + sh.y), ty = tanhf(t01.y * sc.y + sh.y);
    float hz = tanhf(h23.x * sc.z + sh.z), tz = tanhf(t23.x * sc.z + sh.z);
    float hw = tanhf(h23.y * sc.w + sh.w), tw = tanhf(t23.y * sc.w + sh.w);
    float p = fabsf(hx + rv.x - tx) + fabsf(hy + rv.y - ty) +
              fabsf(hz + rv.z - tz) + fabsf(hw + rv.w - tw);
#pragma unroll
    for (int o = 16; o; o >>= 1) p += __shfl_xor_sync(0xffffffffu, p, o);
    if (lane == 0) out[t] = p;
}

// ================= host side =================
static float* sym_addr_f(const void* sym) {
    void* p = nullptr;
    cudaGetSymbolAddress(&p, sym);
    return reinterpret_cast<float*>(p);
}
static __half* sym_addr_h(const void* sym) {
    void* p = nullptr;
    cudaGetSymbolAddress(&p, sym);
    return reinterpret_cast<__half*>(p);
}

extern "C" void kernel_launch(void* const* d_in, const int* in_sizes, int n_in,
                              void* d_out, int out_size) {
    (void)in_sizes; (void)n_in; (void)out_size;
    const float* entity = (const float*)d_in[0];
    const float* bases  = (const float*)d_in[1];
    const float* coeff  = (const float*)d_in[2];
    const float* selfr  = (const float*)d_in[3];
    const float* W1     = (const float*)d_in[4];
    const float* relw1  = (const float*)d_in[5];
    const float* g1     = (const float*)d_in[6];
    const float* b1     = (const float*)d_in[7];
    const float* W2     = (const float*)d_in[8];
    const float* relw2  = (const float*)d_in[9];
    const float* g2     = (const float*)d_in[10];
    const float* b2     = (const float*)d_in[11];
    const int* edge_index = (const int*)d_in[13];
    const int* edge_type  = (const int*)d_in[14];
    const int* yv         = (const int*)d_in[15];
    const int* triples    = (const int*)d_in[16];
    float* out = (float*)d_out;

    float* p_r0 = sym_addr_f(g_r0);
    float* p_r1 = sym_addr_f(g_r1);
    float* p_r2 = sym_addr_f(g_r2);
    float* p_sums = sym_addr_f(g_sums);
    float* p_sumsq = sym_addr_f(g_sumsq);
    __half* p_rh = sym_addr_h(g_rh);
    __half* p_Wh = sym_addr_h(g_Wh);
    __half* p_X1h = sym_addr_h(g_X1h);
    __half* p_X2h = sym_addr_h(g_X2h);

    static cudaStream_t sA = nullptr;
    static cudaEvent_t evFork = nullptr, evPrep = nullptr,
                       evA1 = nullptr, evRel1 = nullptr,
                       evA2 = nullptr, evRel2 = nullptr;
    if (!sA) {
        cudaStreamCreateWithFlags(&sA, cudaStreamNonBlocking);
        cudaEventCreateWithFlags(&evFork, cudaEventDisableTiming);
        cudaEventCreateWithFlags(&evPrep, cudaEventDisableTiming);
        cudaEventCreateWithFlags(&evA1, cudaEventDisableTiming);
        cudaEventCreateWithFlags(&evRel1, cudaEventDisableTiming);
        cudaEventCreateWithFlags(&evA2, cudaEventDisableTiming);
        cudaEventCreateWithFlags(&evRel2, cudaEventDisableTiming);
    }

    cudaFuncSetAttribute(k_gemm, cudaFuncAttributeMaxDynamicSharedMemorySize, SMEM_DYN);

    // ---- r0 + deg zero (needed by CSR hist) ----
    k_r0z<<<201 + (N_ENT + 255) / 256, 256>>>(coeff, bases, selfr);

    // fork: prep (W + entity fp16 + stats zero) runs concurrent with CSR build
    cudaEventRecord(evFork, 0);
    cudaStreamWaitEvent(sA, evFork, 0);
    k_prep<<<6 + (N_ENT * D / 4 + 255) / 256, 256, 0, sA>>>(W1, W2, entity);
    cudaEventRecord(evPrep, sA);

    k_hist<<<(N_EDGES_C + 255) / 256, 256>>>(edge_index);
    k_scan1<<<SCAN_BLKS, 256>>>();
    k_scan3<<<(N_ENT + 255) / 256, 256>>>();
    k_perm<<<(N_EDGES_C + 255) / 256, 256>>>(edge_index, edge_type, yv);
    cudaStreamWaitEvent(0, evPrep, 0);           // join before aggregation

    // ---- layer 1 ----
    k_aggr<<<N_ENT / 8, 256>>>();
    cudaEventRecord(evA1, 0);
    cudaStreamWaitEvent(sA, evA1, 0);            // rel1 overwrites g_rh: wait aggr1
    k_relgemv<<<N_RELS, 128, 0, sA>>>(p_r0, relw1, p_r1, p_rh);
    cudaEventRecord(evRel1, sA);
    k_gemm<<<GEMM_BLKS, 128, SMEM_DYN>>>(p_X1h, p_Wh, p_sums, p_sumsq);
    k_bntanh<<<782, 256>>>(p_X1h, g1, b1);       // local finalize; writes g_xh
    cudaStreamWaitEvent(0, evRel1, 0);           // aggr2 reads new g_rh

    // ---- layer 2 ----
    k_aggr<<<N_ENT / 8, 256>>>();
    cudaEventRecord(evA2, 0);
    cudaStreamWaitEvent(sA, evA2, 0);
    k_relgemv<<<N_RELS, 128, 0, sA>>>(p_r1, relw2, p_r2, nullptr);
    cudaEventRecord(evRel2, sA);
    k_gemm<<<GEMM_BLKS, 128, SMEM_DYN>>>(p_X2h, p_Wh + 3 * D * D, p_sums + D, p_sumsq + D);
    cudaStreamWaitEvent(0, evRel2, 0);           // score reads g_r2

    // ---- scoring (local layer-2 finalize inside) ----
    k_score<<<N_TRIPLES_C / 8, 256>>>(triples, g2, b2, out);
}